// round 1
// baseline (speedup 1.0000x reference)
#include <cuda_runtime.h>
#include <math.h>

// Problem constants (fixed by setup_inputs)
#define DIM   1536
#define S_TOK 1560
#define NH    12
#define HD    128
#define CUR   9360          // current_start
#define L_TOT 10920         // KV window length (w0 = 0)
#define W_GRID 52
#define SCALE 0.08838834764831845f  // 1/sqrt(128)

// Scratch (allocation-free: __device__ globals)
__device__ float g_q[S_TOK * DIM];
__device__ float g_k[S_TOK * DIM];
__device__ float g_v[S_TOK * DIM];
__device__ float g_o[S_TOK * DIM];

// ---------------------------------------------------------------------------
// C[M, DIM] = A[M, DIM] @ B[DIM, DIM]^T + bias   (B row-major, weights layout)
// 128x128 block tile, BK=16, 8x8 per thread, fp32.
// ---------------------------------------------------------------------------
__global__ __launch_bounds__(256, 2)
void gemm_bias_kernel(const float* __restrict__ A, const float* __restrict__ B,
                      const float* __restrict__ bias, float* __restrict__ C,
                      int M) {
    __shared__ float As[16][132];
    __shared__ float Bs[16][132];
    const int tid = threadIdx.x;
    const int m0 = blockIdx.y * 128;
    const int n0 = blockIdx.x * 128;
    const int tm = (tid >> 4) * 8;
    const int tn = (tid & 15) * 8;
    const int lr = tid >> 2;
    const int lc = (tid & 3) * 4;

    float acc[8][8];
#pragma unroll
    for (int i = 0; i < 8; i++)
#pragma unroll
        for (int j = 0; j < 8; j++) acc[i][j] = 0.f;

    for (int k0 = 0; k0 < DIM; k0 += 16) {
#pragma unroll
        for (int h = 0; h < 2; h++) {
            int row = m0 + lr + h * 64;
            float4 v = make_float4(0.f, 0.f, 0.f, 0.f);
            if (row < M) v = *(const float4*)(A + (size_t)row * DIM + k0 + lc);
            As[lc + 0][lr + h * 64] = v.x;
            As[lc + 1][lr + h * 64] = v.y;
            As[lc + 2][lr + h * 64] = v.z;
            As[lc + 3][lr + h * 64] = v.w;
        }
#pragma unroll
        for (int h = 0; h < 2; h++) {
            int row = n0 + lr + h * 64;  // N = DIM, always in range
            float4 v = *(const float4*)(B + (size_t)row * DIM + k0 + lc);
            Bs[lc + 0][lr + h * 64] = v.x;
            Bs[lc + 1][lr + h * 64] = v.y;
            Bs[lc + 2][lr + h * 64] = v.z;
            Bs[lc + 3][lr + h * 64] = v.w;
        }
        __syncthreads();
#pragma unroll
        for (int kk = 0; kk < 16; kk++) {
            float a[8], b[8];
            *(float4*)&a[0] = *(const float4*)&As[kk][tm];
            *(float4*)&a[4] = *(const float4*)&As[kk][tm + 4];
            *(float4*)&b[0] = *(const float4*)&Bs[kk][tn];
            *(float4*)&b[4] = *(const float4*)&Bs[kk][tn + 4];
#pragma unroll
            for (int i = 0; i < 8; i++)
#pragma unroll
                for (int j = 0; j < 8; j++) acc[i][j] += a[i] * b[j];
        }
        __syncthreads();
    }
#pragma unroll
    for (int i = 0; i < 8; i++) {
        int row = m0 + tm + i;
        if (row < M) {
#pragma unroll
            for (int j = 0; j < 8; j++)
                C[(size_t)row * DIM + n0 + tn + j] = acc[i][j] + bias[n0 + tn + j];
        }
    }
}

// ---------------------------------------------------------------------------
// In-place rmsnorm (over full DIM) + RoPE per head. One block per token row.
// Token s -> (h = s/52, w = s%52); table row: c<22 -> 6 (start_frame),
// 22<=c<43 -> h, 43<=c<64 -> w. Tables are (1024, 64) row-major.
// ---------------------------------------------------------------------------
__global__ __launch_bounds__(256)
void norm_rope_kernel(float* __restrict__ t, const float* __restrict__ g,
                      const float* __restrict__ fcos, const float* __restrict__ fsin) {
    const int s = blockIdx.x;
    float* row = t + (size_t)s * DIM;
    __shared__ float red[256];

    float ss = 0.f;
    for (int i = threadIdx.x; i < DIM; i += 256) {
        float v = row[i];
        ss += v * v;
    }
    red[threadIdx.x] = ss;
    __syncthreads();
    for (int off = 128; off > 0; off >>= 1) {
        if (threadIdx.x < off) red[threadIdx.x] += red[threadIdx.x + off];
        __syncthreads();
    }
    const float scale = rsqrtf(red[0] * (1.0f / DIM) + 1e-6f);

    const int hh = s / W_GRID;
    const int ww = s % W_GRID;
    for (int p = threadIdx.x; p < NH * 64; p += 256) {
        const int head = p >> 6;
        const int c = p & 63;
        const int trow = (c < 22) ? 6 : ((c < 43) ? hh : ww);
        const float cv = fcos[trow * 64 + c];
        const float sv = fsin[trow * 64 + c];
        const int base = head * HD + 2 * c;
        const float xr = row[base] * scale * g[base];
        const float xi = row[base + 1] * scale * g[base + 1];
        row[base]     = xr * cv - xi * sv;
        row[base + 1] = xr * sv + xi * cv;
    }
}

// ---------------------------------------------------------------------------
// Flash attention: 64 q-rows x 64 k-rows per tile, HD=128, online softmax.
// K/V source: cache for kidx < CUR, fresh (RoPE'd) scratch for kidx >= CUR.
// grid = (ceil(S/64), NH), 256 threads (tx = tid&15, ty = tid>>4).
// ---------------------------------------------------------------------------
#define QS_STRIDE 132
#define PS_STRIDE 68
#define ATTN_SMEM ((2 * 64 * QS_STRIDE + 64 * PS_STRIDE + 3 * 64) * 4)

__global__ __launch_bounds__(256, 2)
void attn_kernel(const float* __restrict__ q, const float* __restrict__ knew,
                 const float* __restrict__ vnew, const float* __restrict__ ck,
                 const float* __restrict__ cv, float* __restrict__ out) {
    extern __shared__ float sm[];
    float* Qs    = sm;                       // 64 x 132
    float* Ks    = Qs + 64 * QS_STRIDE;      // 64 x 132 (reused for V)
    float* Ps    = Ks + 64 * QS_STRIDE;      // 64 x 68
    float* row_m = Ps + 64 * PS_STRIDE;      // 64
    float* row_l = row_m + 64;               // 64
    float* row_a = row_l + 64;               // 64

    const int head = blockIdx.y;
    const int q0 = blockIdx.x * 64;
    const int tid = threadIdx.x;
    const int tx = tid & 15, ty = tid >> 4;

    // Load Q tile (zero-pad tail rows)
    {
        const int r = tid >> 2;
        const int c4 = (tid & 3) * 32;
        const int srow = q0 + r;
        const bool valid = srow < S_TOK;
        const float* src = q + (size_t)srow * DIM + head * HD;
#pragma unroll
        for (int m2 = 0; m2 < 8; m2++) {
            int d = c4 + m2 * 4;
            float4 v = valid ? *(const float4*)(src + d) : make_float4(0.f, 0.f, 0.f, 0.f);
            *(float4*)&Qs[r * QS_STRIDE + d] = v;
        }
    }
    if (tid < 64) { row_m[tid] = -1e30f; row_l[tid] = 0.f; }

    float acc[4][8];
#pragma unroll
    for (int i = 0; i < 4; i++)
#pragma unroll
        for (int j = 0; j < 8; j++) acc[i][j] = 0.f;

    __syncthreads();

    const int NT = (L_TOT + 63) / 64;  // 171
    for (int t = 0; t < NT; t++) {
        const int kbase = t * 64;
        // ---- load K tile ----
        {
            const int r = tid >> 2;
            const int c4 = (tid & 3) * 32;
            const int kidx = kbase + r;
            const bool valid = kidx < L_TOT;
            const float* src = (kidx < CUR)
                ? (ck + ((size_t)kidx * NH + head) * HD)
                : (knew + (size_t)(kidx - CUR) * DIM + head * HD);
#pragma unroll
            for (int m2 = 0; m2 < 8; m2++) {
                int d = c4 + m2 * 4;
                float4 v = valid ? *(const float4*)(src + d) : make_float4(0.f, 0.f, 0.f, 0.f);
                *(float4*)&Ks[r * QS_STRIDE + d] = v;
            }
        }
        __syncthreads();

        // ---- scores: q rows ty*4+i  x  k rows tx + j*16 ----
        float sc[4][4];
#pragma unroll
        for (int i = 0; i < 4; i++)
#pragma unroll
            for (int j = 0; j < 4; j++) sc[i][j] = 0.f;

        for (int d = 0; d < HD; d += 4) {
            float4 qa[4], kb[4];
#pragma unroll
            for (int i = 0; i < 4; i++) qa[i] = *(const float4*)&Qs[(ty * 4 + i) * QS_STRIDE + d];
#pragma unroll
            for (int j = 0; j < 4; j++) kb[j] = *(const float4*)&Ks[(tx + j * 16) * QS_STRIDE + d];
#pragma unroll
            for (int i = 0; i < 4; i++)
#pragma unroll
                for (int j = 0; j < 4; j++) {
                    sc[i][j] += qa[i].x * kb[j].x;
                    sc[i][j] += qa[i].y * kb[j].y;
                    sc[i][j] += qa[i].z * kb[j].z;
                    sc[i][j] += qa[i].w * kb[j].w;
                }
        }
#pragma unroll
        for (int i = 0; i < 4; i++)
#pragma unroll
            for (int j = 0; j < 4; j++) {
                const int kidx = kbase + tx + j * 16;
                float v = sc[i][j] * SCALE;
                if (kidx >= L_TOT) v = -1e30f;
                Ps[(ty * 4 + i) * PS_STRIDE + tx + j * 16] = v;
            }
        __syncthreads();

        // ---- softmax update (4 threads per row) + V tile load (reuses Ks) ----
        {
            const int r = tid >> 2;
            const int part = tid & 3;
            float mx = -1e30f;
#pragma unroll
            for (int jj = 0; jj < 16; jj++) mx = fmaxf(mx, Ps[r * PS_STRIDE + part * 16 + jj]);
            mx = fmaxf(mx, __shfl_xor_sync(0xffffffffu, mx, 1));
            mx = fmaxf(mx, __shfl_xor_sync(0xffffffffu, mx, 2));
            const float m_old = row_m[r];
            const float m_new = fmaxf(m_old, mx);
            float sum = 0.f;
#pragma unroll
            for (int jj = 0; jj < 16; jj++) {
                float p = __expf(Ps[r * PS_STRIDE + part * 16 + jj] - m_new);
                Ps[r * PS_STRIDE + part * 16 + jj] = p;
                sum += p;
            }
            sum += __shfl_xor_sync(0xffffffffu, sum, 1);
            sum += __shfl_xor_sync(0xffffffffu, sum, 2);
            if (part == 0) {
                const float al = __expf(m_old - m_new);
                row_a[r] = al;
                row_l[r] = row_l[r] * al + sum;
                row_m[r] = m_new;
            }
        }
        {   // V load (Ks already fully consumed by score phase before last sync)
            const int r = tid >> 2;
            const int c4 = (tid & 3) * 32;
            const int kidx = kbase + r;
            const bool valid = kidx < L_TOT;
            const float* src = (kidx < CUR)
                ? (cv + ((size_t)kidx * NH + head) * HD)
                : (vnew + (size_t)(kidx - CUR) * DIM + head * HD);
#pragma unroll
            for (int m2 = 0; m2 < 8; m2++) {
                int d = c4 + m2 * 4;
                float4 v = valid ? *(const float4*)(src + d) : make_float4(0.f, 0.f, 0.f, 0.f);
                *(float4*)&Ks[r * QS_STRIDE + d] = v;
            }
        }
        __syncthreads();

        // ---- O update: rows ty*4+i, cols tx*8..tx*8+7 ----
        {
            float al[4];
#pragma unroll
            for (int i = 0; i < 4; i++) al[i] = row_a[ty * 4 + i];
#pragma unroll
            for (int i = 0; i < 4; i++)
#pragma unroll
                for (int j = 0; j < 8; j++) acc[i][j] *= al[i];

            for (int kk = 0; kk < 64; kk++) {
                float p[4];
#pragma unroll
                for (int i = 0; i < 4; i++) p[i] = Ps[(ty * 4 + i) * PS_STRIDE + kk];
                float4 v0 = *(const float4*)&Ks[kk * QS_STRIDE + tx * 8];
                float4 v1 = *(const float4*)&Ks[kk * QS_STRIDE + tx * 8 + 4];
#pragma unroll
                for (int i = 0; i < 4; i++) {
                    acc[i][0] += p[i] * v0.x;
                    acc[i][1] += p[i] * v0.y;
                    acc[i][2] += p[i] * v0.z;
                    acc[i][3] += p[i] * v0.w;
                    acc[i][4] += p[i] * v1.x;
                    acc[i][5] += p[i] * v1.y;
                    acc[i][6] += p[i] * v1.z;
                    acc[i][7] += p[i] * v1.w;
                }
            }
        }
        __syncthreads();
    }

    // ---- epilogue ----
#pragma unroll
    for (int i = 0; i < 4; i++) {
        const int srow = q0 + ty * 4 + i;
        if (srow < S_TOK) {
            const float inv = 1.0f / row_l[ty * 4 + i];
            float4 o0, o1;
            o0.x = acc[i][0] * inv; o0.y = acc[i][1] * inv;
            o0.z = acc[i][2] * inv; o0.w = acc[i][3] * inv;
            o1.x = acc[i][4] * inv; o1.y = acc[i][5] * inv;
            o1.z = acc[i][6] * inv; o1.w = acc[i][7] * inv;
            float* dst = out + (size_t)srow * DIM + head * HD + tx * 8;
            *(float4*)dst = o0;
            *(float4*)(dst + 4) = o1;
        }
    }
}

// ---------------------------------------------------------------------------
extern "C" void kernel_launch(void* const* d_in, const int* in_sizes, int n_in,
                              void* d_out, int out_size) {
    (void)in_sizes; (void)n_in; (void)out_size;
    const float* x    = (const float*)d_in[0];
    const float* wq   = (const float*)d_in[1];
    const float* bq   = (const float*)d_in[2];
    const float* wk   = (const float*)d_in[3];
    const float* bk   = (const float*)d_in[4];
    const float* wv   = (const float*)d_in[5];
    const float* bv   = (const float*)d_in[6];
    const float* wo   = (const float*)d_in[7];
    const float* bo   = (const float*)d_in[8];
    const float* gq   = (const float*)d_in[9];
    const float* gk   = (const float*)d_in[10];
    const float* fcos = (const float*)d_in[11];
    const float* fsin = (const float*)d_in[12];
    const float* ck   = (const float*)d_in[13];
    const float* cvv  = (const float*)d_in[14];

    float *q, *k, *v, *o;
    cudaGetSymbolAddress((void**)&q, g_q);
    cudaGetSymbolAddress((void**)&k, g_k);
    cudaGetSymbolAddress((void**)&v, g_v);
    cudaGetSymbolAddress((void**)&o, g_o);

    cudaFuncSetAttribute(attn_kernel, cudaFuncAttributeMaxDynamicSharedMemorySize,
                         ATTN_SMEM);

    dim3 ggrid(DIM / 128, (S_TOK + 127) / 128);  // (12, 13)
    gemm_bias_kernel<<<ggrid, 256>>>(x, wq, bq, q, S_TOK);
    gemm_bias_kernel<<<ggrid, 256>>>(x, wk, bk, k, S_TOK);
    gemm_bias_kernel<<<ggrid, 256>>>(x, wv, bv, v, S_TOK);

    norm_rope_kernel<<<S_TOK, 256>>>(q, gq, fcos, fsin);
    norm_rope_kernel<<<S_TOK, 256>>>(k, gk, fcos, fsin);

    dim3 agrid((S_TOK + 63) / 64, NH);  // (25, 12)
    attn_kernel<<<agrid, 256, ATTN_SMEM>>>(q, k, v, ck, cvv, o);

    gemm_bias_kernel<<<ggrid, 256>>>(o, wo, bo, (float*)d_out, S_TOK);
}

// round 2
// speedup vs baseline: 1.5192x; 1.5192x over previous
#include <cuda_runtime.h>
#include <math.h>

// Problem constants (fixed by setup_inputs)
#define DIM   1536
#define S_TOK 1560
#define NH    12
#define HD    128
#define CUR   9360          // current_start
#define L_TOT 10920         // KV window length (w0 = 0)
#define W_GRID 52
#define SCALE 0.08838834764831845f  // 1/sqrt(128)

// Scratch (allocation-free: __device__ globals)
__device__ float g_q[S_TOK * DIM];
__device__ float g_k[S_TOK * DIM];
__device__ float g_v[S_TOK * DIM];
__device__ float g_o[S_TOK * DIM];

// ---------------------------------------------------------------------------
// fp32 SIMT GEMM (projections): C[M,DIM] = A[M,DIM] @ B[DIM,DIM]^T + bias
// ---------------------------------------------------------------------------
__global__ __launch_bounds__(256, 2)
void gemm_bias_kernel(const float* __restrict__ A, const float* __restrict__ B,
                      const float* __restrict__ bias, float* __restrict__ C,
                      int M) {
    __shared__ float As[16][132];
    __shared__ float Bs[16][132];
    const int tid = threadIdx.x;
    const int m0 = blockIdx.y * 128;
    const int n0 = blockIdx.x * 128;
    const int tm = (tid >> 4) * 8;
    const int tn = (tid & 15) * 8;
    const int lr = tid >> 2;
    const int lc = (tid & 3) * 4;

    float acc[8][8];
#pragma unroll
    for (int i = 0; i < 8; i++)
#pragma unroll
        for (int j = 0; j < 8; j++) acc[i][j] = 0.f;

    for (int k0 = 0; k0 < DIM; k0 += 16) {
#pragma unroll
        for (int h = 0; h < 2; h++) {
            int row = m0 + lr + h * 64;
            float4 v = make_float4(0.f, 0.f, 0.f, 0.f);
            if (row < M) v = *(const float4*)(A + (size_t)row * DIM + k0 + lc);
            As[lc + 0][lr + h * 64] = v.x;
            As[lc + 1][lr + h * 64] = v.y;
            As[lc + 2][lr + h * 64] = v.z;
            As[lc + 3][lr + h * 64] = v.w;
        }
#pragma unroll
        for (int h = 0; h < 2; h++) {
            int row = n0 + lr + h * 64;
            float4 v = *(const float4*)(B + (size_t)row * DIM + k0 + lc);
            Bs[lc + 0][lr + h * 64] = v.x;
            Bs[lc + 1][lr + h * 64] = v.y;
            Bs[lc + 2][lr + h * 64] = v.z;
            Bs[lc + 3][lr + h * 64] = v.w;
        }
        __syncthreads();
#pragma unroll
        for (int kk = 0; kk < 16; kk++) {
            float a[8], b[8];
            *(float4*)&a[0] = *(const float4*)&As[kk][tm];
            *(float4*)&a[4] = *(const float4*)&As[kk][tm + 4];
            *(float4*)&b[0] = *(const float4*)&Bs[kk][tn];
            *(float4*)&b[4] = *(const float4*)&Bs[kk][tn + 4];
#pragma unroll
            for (int i = 0; i < 8; i++)
#pragma unroll
                for (int j = 0; j < 8; j++) acc[i][j] += a[i] * b[j];
        }
        __syncthreads();
    }
#pragma unroll
    for (int i = 0; i < 8; i++) {
        int row = m0 + tm + i;
        if (row < M) {
#pragma unroll
            for (int j = 0; j < 8; j++)
                C[(size_t)row * DIM + n0 + tn + j] = acc[i][j] + bias[n0 + tn + j];
        }
    }
}

// ---------------------------------------------------------------------------
// In-place rmsnorm + RoPE (unchanged)
// ---------------------------------------------------------------------------
__global__ __launch_bounds__(256)
void norm_rope_kernel(float* __restrict__ t, const float* __restrict__ g,
                      const float* __restrict__ fcos, const float* __restrict__ fsin) {
    const int s = blockIdx.x;
    float* row = t + (size_t)s * DIM;
    __shared__ float red[256];

    float ss = 0.f;
    for (int i = threadIdx.x; i < DIM; i += 256) {
        float v = row[i];
        ss += v * v;
    }
    red[threadIdx.x] = ss;
    __syncthreads();
    for (int off = 128; off > 0; off >>= 1) {
        if (threadIdx.x < off) red[threadIdx.x] += red[threadIdx.x + off];
        __syncthreads();
    }
    const float scale = rsqrtf(red[0] * (1.0f / DIM) + 1e-6f);

    const int hh = s / W_GRID;
    const int ww = s % W_GRID;
    for (int p = threadIdx.x; p < NH * 64; p += 256) {
        const int head = p >> 6;
        const int c = p & 63;
        const int trow = (c < 22) ? 6 : ((c < 43) ? hh : ww);
        const float cv = fcos[trow * 64 + c];
        const float sv = fsin[trow * 64 + c];
        const int base = head * HD + 2 * c;
        const float xr = row[base] * scale * g[base];
        const float xi = row[base + 1] * scale * g[base + 1];
        row[base]     = xr * cv - xi * sv;
        row[base + 1] = xr * sv + xi * cv;
    }
}

// ---------------------------------------------------------------------------
// tf32 tensor-core flash attention.
// Tile: 64 q x 64 k, HD=128. 256 threads = 8 warps, warp w:
//   score phase: q rows (w>>1)*16..+16, k cols (w&1)*32..+32
//   PV phase:    q rows (w>>1)*16..+16, hd cols (w&1)*64..+64
// mma.sync.aligned.m16n8k8.row.col.f32.tf32.tf32.f32 with explicit cvt.rna.
// ---------------------------------------------------------------------------
#define BQ 64
#define BK 64
#define KSTR 132   // u32 stride for Q/KV tiles (132%32==4 -> conflict-free frags)
#define PSTR 68

struct AttnSmem {
    unsigned int Qs[BQ * KSTR];
    unsigned int KVs[BK * KSTR];
    float Ps[BQ * PSTR];          // fp32 scores; rewritten as tf32 bits post-softmax
    float row_m[BQ];
    float row_l[BQ];
    float row_a[BQ];
};
#define ATTN_SMEM ((int)sizeof(AttnSmem))

__device__ __forceinline__ unsigned int f2tf(float f) {
    unsigned int u;
    asm("cvt.rna.tf32.f32 %0, %1;" : "=r"(u) : "f"(f));
    return u;
}

__device__ __forceinline__ void mma_tf32(float c[4], unsigned int a0, unsigned int a1,
                                         unsigned int a2, unsigned int a3,
                                         unsigned int b0, unsigned int b1) {
    asm("mma.sync.aligned.m16n8k8.row.col.f32.tf32.tf32.f32 "
        "{%0,%1,%2,%3}, {%4,%5,%6,%7}, {%8,%9}, {%0,%1,%2,%3};"
        : "+f"(c[0]), "+f"(c[1]), "+f"(c[2]), "+f"(c[3])
        : "r"(a0), "r"(a1), "r"(a2), "r"(a3), "r"(b0), "r"(b1));
}

__global__ __launch_bounds__(256, 2)
void attn_tc_kernel(const float* __restrict__ q, const float* __restrict__ knew,
                    const float* __restrict__ vnew, const float* __restrict__ ck,
                    const float* __restrict__ cv, float* __restrict__ out) {
    extern __shared__ char smraw[];
    AttnSmem* sm = (AttnSmem*)smraw;

    const int head = blockIdx.y;
    const int q0 = blockIdx.x * BQ;
    const int tid = threadIdx.x;
    const int lane = tid & 31;
    const int w = tid >> 5;
    const int g = lane >> 2;
    const int tg = lane & 3;
    const int wq = (w >> 1) * 16;
    const int wk = (w & 1) * 32;
    const int wn = (w & 1) * 64;

    // ---- load Q tile (tf32-converted), zero-pad tail rows ----
    {
        const int r = tid >> 2;
        const int cbase = (tid & 3) * 32;
        const int srow = q0 + r;
        const bool valid = srow < S_TOK;
        const float* src = q + (size_t)srow * DIM + head * HD;
#pragma unroll
        for (int m2 = 0; m2 < 8; m2++) {
            int d = cbase + m2 * 4;
            float4 v = valid ? *(const float4*)(src + d) : make_float4(0.f, 0.f, 0.f, 0.f);
            uint4 u = make_uint4(f2tf(v.x), f2tf(v.y), f2tf(v.z), f2tf(v.w));
            *(uint4*)&sm->Qs[r * KSTR + d] = u;
        }
    }
    if (tid < BQ) { sm->row_m[tid] = -1e30f; sm->row_l[tid] = 0.f; }

    float acc[8][4];
#pragma unroll
    for (int i = 0; i < 8; i++)
#pragma unroll
        for (int j = 0; j < 4; j++) acc[i][j] = 0.f;

    __syncthreads();

    const int NT = (L_TOT + BK - 1) / BK;  // 171
    for (int t = 0; t < NT; t++) {
        const int kbase = t * BK;

        // ---- load K tile (tf32) ----
        {
            const int r = tid >> 2;
            const int cbase = (tid & 3) * 32;
            const int kidx = kbase + r;
            const bool valid = kidx < L_TOT;
            const float* src = (kidx < CUR)
                ? (ck + ((size_t)kidx * NH + head) * HD)
                : (knew + (size_t)(kidx - CUR) * DIM + head * HD);
#pragma unroll
            for (int m2 = 0; m2 < 8; m2++) {
                int d = cbase + m2 * 4;
                float4 v = valid ? *(const float4*)(src + d) : make_float4(0.f, 0.f, 0.f, 0.f);
                uint4 u = make_uint4(f2tf(v.x), f2tf(v.y), f2tf(v.z), f2tf(v.w));
                *(uint4*)&sm->KVs[r * KSTR + d] = u;
            }
        }
        __syncthreads();

        // ---- scores: warp computes 16q x 32k via 16 k-steps x 4 n-frags ----
        {
            float sc[4][4];
#pragma unroll
            for (int nf = 0; nf < 4; nf++)
#pragma unroll
                for (int j = 0; j < 4; j++) sc[nf][j] = 0.f;

#pragma unroll 4
            for (int kf = 0; kf < 16; kf++) {
                const int kc = kf * 8;
                unsigned int a0 = sm->Qs[(wq + g) * KSTR + kc + tg];
                unsigned int a1 = sm->Qs[(wq + g + 8) * KSTR + kc + tg];
                unsigned int a2 = sm->Qs[(wq + g) * KSTR + kc + tg + 4];
                unsigned int a3 = sm->Qs[(wq + g + 8) * KSTR + kc + tg + 4];
#pragma unroll
                for (int nf = 0; nf < 4; nf++) {
                    unsigned int b0 = sm->KVs[(wk + nf * 8 + g) * KSTR + kc + tg];
                    unsigned int b1 = sm->KVs[(wk + nf * 8 + g) * KSTR + kc + tg + 4];
                    mma_tf32(sc[nf], a0, a1, a2, a3, b0, b1);
                }
            }
            // write scores (scaled, masked) to Ps as fp32
#pragma unroll
            for (int nf = 0; nf < 4; nf++) {
                const int col = wk + nf * 8 + 2 * tg;
                const int kidx = kbase + col;
                const bool v0 = kidx < L_TOT;
                const bool v1 = kidx + 1 < L_TOT;
                sm->Ps[(wq + g) * PSTR + col]         = v0 ? sc[nf][0] * SCALE : -1e30f;
                sm->Ps[(wq + g) * PSTR + col + 1]     = v1 ? sc[nf][1] * SCALE : -1e30f;
                sm->Ps[(wq + g + 8) * PSTR + col]     = v0 ? sc[nf][2] * SCALE : -1e30f;
                sm->Ps[(wq + g + 8) * PSTR + col + 1] = v1 ? sc[nf][3] * SCALE : -1e30f;
            }
        }
        __syncthreads();

        // ---- softmax update (4 threads/row), writing exp(p) back as tf32 bits ----
        {
            const int r = tid >> 2;
            const int part = tid & 3;
            float mx = -1e30f;
#pragma unroll
            for (int jj = 0; jj < 16; jj++)
                mx = fmaxf(mx, sm->Ps[r * PSTR + part * 16 + jj]);
            mx = fmaxf(mx, __shfl_xor_sync(0xffffffffu, mx, 1));
            mx = fmaxf(mx, __shfl_xor_sync(0xffffffffu, mx, 2));
            const float m_old = sm->row_m[r];
            const float m_new = fmaxf(m_old, mx);
            float sum = 0.f;
            unsigned int* Pu = (unsigned int*)sm->Ps;
#pragma unroll
            for (int jj = 0; jj < 16; jj++) {
                float p = __expf(sm->Ps[r * PSTR + part * 16 + jj] - m_new);
                Pu[r * PSTR + part * 16 + jj] = f2tf(p);
                sum += p;
            }
            sum += __shfl_xor_sync(0xffffffffu, sum, 1);
            sum += __shfl_xor_sync(0xffffffffu, sum, 2);
            if (part == 0) {
                const float al = __expf(m_old - m_new);
                sm->row_a[r] = al;
                sm->row_l[r] = sm->row_l[r] * al + sum;
                sm->row_m[r] = m_new;
            }
        }
        // ---- load V tile into KVs (score phase done with K) ----
        {
            const int r = tid >> 2;
            const int cbase = (tid & 3) * 32;
            const int kidx = kbase + r;
            const bool valid = kidx < L_TOT;
            const float* src = (kidx < CUR)
                ? (cv + ((size_t)kidx * NH + head) * HD)
                : (vnew + (size_t)(kidx - CUR) * DIM + head * HD);
#pragma unroll
            for (int m2 = 0; m2 < 8; m2++) {
                int d = cbase + m2 * 4;
                float4 v = valid ? *(const float4*)(src + d) : make_float4(0.f, 0.f, 0.f, 0.f);
                uint4 u = make_uint4(f2tf(v.x), f2tf(v.y), f2tf(v.z), f2tf(v.w));
                *(uint4*)&sm->KVs[r * KSTR + d] = u;
            }
        }
        __syncthreads();

        // ---- PV: warp computes 16q x 64hd over 64 k ----
        {
            const float aG = sm->row_a[wq + g];
            const float aG8 = sm->row_a[wq + g + 8];
#pragma unroll
            for (int nf = 0; nf < 8; nf++) {
                acc[nf][0] *= aG;  acc[nf][1] *= aG;
                acc[nf][2] *= aG8; acc[nf][3] *= aG8;
            }
            const unsigned int* Pu = (const unsigned int*)sm->Ps;
#pragma unroll
            for (int kf = 0; kf < 8; kf++) {
                const int kc = kf * 8;
                unsigned int a0 = Pu[(wq + g) * PSTR + kc + tg];
                unsigned int a1 = Pu[(wq + g + 8) * PSTR + kc + tg];
                unsigned int a2 = Pu[(wq + g) * PSTR + kc + tg + 4];
                unsigned int a3 = Pu[(wq + g + 8) * PSTR + kc + tg + 4];
#pragma unroll
                for (int nf = 0; nf < 8; nf++) {
                    unsigned int b0 = sm->KVs[(kc + tg) * KSTR + wn + nf * 8 + g];
                    unsigned int b1 = sm->KVs[(kc + tg + 4) * KSTR + wn + nf * 8 + g];
                    mma_tf32(acc[nf], a0, a1, a2, a3, b0, b1);
                }
            }
        }
        __syncthreads();
    }

    // ---- epilogue ----
    {
        const float inv  = 1.0f / sm->row_l[wq + g];
        const float inv8 = 1.0f / sm->row_l[wq + g + 8];
        const int row  = q0 + wq + g;
        const int row8 = row + 8;
#pragma unroll
        for (int nf = 0; nf < 8; nf++) {
            const int col = head * HD + wn + nf * 8 + 2 * tg;
            if (row < S_TOK) {
                float2 o0 = make_float2(acc[nf][0] * inv, acc[nf][1] * inv);
                *(float2*)(out + (size_t)row * DIM + col) = o0;
            }
            if (row8 < S_TOK) {
                float2 o1 = make_float2(acc[nf][2] * inv8, acc[nf][3] * inv8);
                *(float2*)(out + (size_t)row8 * DIM + col) = o1;
            }
        }
    }
}

// ---------------------------------------------------------------------------
extern "C" void kernel_launch(void* const* d_in, const int* in_sizes, int n_in,
                              void* d_out, int out_size) {
    (void)in_sizes; (void)n_in; (void)out_size;
    const float* x    = (const float*)d_in[0];
    const float* wq   = (const float*)d_in[1];
    const float* bq   = (const float*)d_in[2];
    const float* wk   = (const float*)d_in[3];
    const float* bk   = (const float*)d_in[4];
    const float* wv   = (const float*)d_in[5];
    const float* bv   = (const float*)d_in[6];
    const float* wo   = (const float*)d_in[7];
    const float* bo   = (const float*)d_in[8];
    const float* gq   = (const float*)d_in[9];
    const float* gk   = (const float*)d_in[10];
    const float* fcos = (const float*)d_in[11];
    const float* fsin = (const float*)d_in[12];
    const float* ck   = (const float*)d_in[13];
    const float* cvv  = (const float*)d_in[14];

    float *q, *k, *v, *o;
    cudaGetSymbolAddress((void**)&q, g_q);
    cudaGetSymbolAddress((void**)&k, g_k);
    cudaGetSymbolAddress((void**)&v, g_v);
    cudaGetSymbolAddress((void**)&o, g_o);

    cudaFuncSetAttribute(attn_tc_kernel, cudaFuncAttributeMaxDynamicSharedMemorySize,
                         ATTN_SMEM);

    dim3 ggrid(DIM / 128, (S_TOK + 127) / 128);  // (12, 13)
    gemm_bias_kernel<<<ggrid, 256>>>(x, wq, bq, q, S_TOK);
    gemm_bias_kernel<<<ggrid, 256>>>(x, wk, bk, k, S_TOK);
    gemm_bias_kernel<<<ggrid, 256>>>(x, wv, bv, v, S_TOK);

    norm_rope_kernel<<<S_TOK, 256>>>(q, gq, fcos, fsin);
    norm_rope_kernel<<<S_TOK, 256>>>(k, gk, fcos, fsin);

    dim3 agrid((S_TOK + 63) / 64, NH);  // (25, 12)
    attn_tc_kernel<<<agrid, 256, ATTN_SMEM>>>(q, k, v, ck, cvv, o);

    gemm_bias_kernel<<<ggrid, 256>>>(o, wo, bo, (float*)d_out, S_TOK);
}

// round 3
// speedup vs baseline: 1.6477x; 1.0846x over previous
#include <cuda_runtime.h>
#include <math.h>

// Problem constants (fixed by setup_inputs)
#define DIM   1536
#define S_TOK 1560
#define NH    12
#define HD    128
#define CUR   9360          // current_start
#define L_TOT 10920         // KV window length (w0 = 0)
#define W_GRID 52
#define SCALE 0.08838834764831845f  // 1/sqrt(128)

// Scratch (allocation-free: __device__ globals)
__device__ float g_q[S_TOK * DIM];
__device__ float g_k[S_TOK * DIM];
__device__ float g_v[S_TOK * DIM];
__device__ float g_o[S_TOK * DIM];

__device__ __forceinline__ unsigned int f2tf(float f) {
    unsigned int u;
    asm("cvt.rna.tf32.f32 %0, %1;" : "=r"(u) : "f"(f));
    return u;
}

__device__ __forceinline__ void mma_tf32(float c[4], unsigned int a0, unsigned int a1,
                                         unsigned int a2, unsigned int a3,
                                         unsigned int b0, unsigned int b1) {
    asm("mma.sync.aligned.m16n8k8.row.col.f32.tf32.tf32.f32 "
        "{%0,%1,%2,%3}, {%4,%5,%6,%7}, {%8,%9}, {%0,%1,%2,%3};"
        : "+f"(c[0]), "+f"(c[1]), "+f"(c[2]), "+f"(c[3])
        : "r"(a0), "r"(a1), "r"(a2), "r"(a3), "r"(b0), "r"(b1));
}

// ---------------------------------------------------------------------------
// tf32 tensor-core GEMM: C[M,DIM] = A[M,DIM] @ B[DIM,DIM]^T + bias
// 128x128 block, BK=32, 256 threads = 8 warps (4x2), warp = 32 rows x 64 cols.
// ---------------------------------------------------------------------------
#define GSTR 36

__global__ __launch_bounds__(256)
void gemm_tf32_kernel(const float* __restrict__ A, const float* __restrict__ B,
                      const float* __restrict__ bias, float* __restrict__ C,
                      int M) {
    __shared__ unsigned int As[128 * GSTR];
    __shared__ unsigned int Bs[128 * GSTR];
    const int tid = threadIdx.x;
    const int m0 = blockIdx.y * 128;
    const int n0 = blockIdx.x * 128;
    const int lane = tid & 31;
    const int w = tid >> 5;
    const int g = lane >> 2;
    const int tg = lane & 3;
    const int wy = w >> 1;       // 0..3
    const int wx = w & 1;        // 0..1
    const int r = tid >> 1;      // 0..127
    const int cbase = (tid & 1) * 16;

    float acc[2][8][4];
#pragma unroll
    for (int mf = 0; mf < 2; mf++)
#pragma unroll
        for (int nf = 0; nf < 8; nf++)
#pragma unroll
            for (int j = 0; j < 4; j++) acc[mf][nf][j] = 0.f;

    const bool avalid = (m0 + r) < M;
    const float* pa = A + (size_t)(m0 + r) * DIM + cbase;
    const float* pb = B + (size_t)(n0 + r) * DIM + cbase;

    for (int k0 = 0; k0 < DIM; k0 += 32) {
#pragma unroll
        for (int i = 0; i < 4; i++) {
            float4 v = avalid ? *(const float4*)(pa + k0 + i * 4)
                              : make_float4(0.f, 0.f, 0.f, 0.f);
            *(uint4*)&As[r * GSTR + cbase + i * 4] =
                make_uint4(f2tf(v.x), f2tf(v.y), f2tf(v.z), f2tf(v.w));
        }
#pragma unroll
        for (int i = 0; i < 4; i++) {
            float4 v = *(const float4*)(pb + k0 + i * 4);
            *(uint4*)&Bs[r * GSTR + cbase + i * 4] =
                make_uint4(f2tf(v.x), f2tf(v.y), f2tf(v.z), f2tf(v.w));
        }
        __syncthreads();
#pragma unroll
        for (int kc = 0; kc < 32; kc += 8) {
            unsigned int a[2][4];
#pragma unroll
            for (int mf = 0; mf < 2; mf++) {
                const int row = wy * 32 + mf * 16 + g;
                a[mf][0] = As[row * GSTR + kc + tg];
                a[mf][1] = As[(row + 8) * GSTR + kc + tg];
                a[mf][2] = As[row * GSTR + kc + tg + 4];
                a[mf][3] = As[(row + 8) * GSTR + kc + tg + 4];
            }
#pragma unroll
            for (int nf = 0; nf < 8; nf++) {
                const int brow = wx * 64 + nf * 8 + g;
                unsigned int b0 = Bs[brow * GSTR + kc + tg];
                unsigned int b1 = Bs[brow * GSTR + kc + tg + 4];
                mma_tf32(acc[0][nf], a[0][0], a[0][1], a[0][2], a[0][3], b0, b1);
                mma_tf32(acc[1][nf], a[1][0], a[1][1], a[1][2], a[1][3], b0, b1);
            }
        }
        __syncthreads();
    }

#pragma unroll
    for (int mf = 0; mf < 2; mf++) {
        const int row = m0 + wy * 32 + mf * 16 + g;
#pragma unroll
        for (int nf = 0; nf < 8; nf++) {
            const int col = n0 + wx * 64 + nf * 8 + 2 * tg;
            const float b0 = bias[col], b1 = bias[col + 1];
            if (row < M)
                *(float2*)(C + (size_t)row * DIM + col) =
                    make_float2(acc[mf][nf][0] + b0, acc[mf][nf][1] + b1);
            if (row + 8 < M)
                *(float2*)(C + (size_t)(row + 8) * DIM + col) =
                    make_float2(acc[mf][nf][2] + b0, acc[mf][nf][3] + b1);
        }
    }
}

// ---------------------------------------------------------------------------
// In-place rmsnorm + RoPE
// ---------------------------------------------------------------------------
__global__ __launch_bounds__(256)
void norm_rope_kernel(float* __restrict__ t, const float* __restrict__ g,
                      const float* __restrict__ fcos, const float* __restrict__ fsin) {
    const int s = blockIdx.x;
    float* row = t + (size_t)s * DIM;
    __shared__ float red[256];

    float ss = 0.f;
    for (int i = threadIdx.x; i < DIM; i += 256) {
        float v = row[i];
        ss += v * v;
    }
    red[threadIdx.x] = ss;
    __syncthreads();
    for (int off = 128; off > 0; off >>= 1) {
        if (threadIdx.x < off) red[threadIdx.x] += red[threadIdx.x + off];
        __syncthreads();
    }
    const float scale = rsqrtf(red[0] * (1.0f / DIM) + 1e-6f);

    const int hh = s / W_GRID;
    const int ww = s % W_GRID;
    for (int p = threadIdx.x; p < NH * 64; p += 256) {
        const int head = p >> 6;
        const int c = p & 63;
        const int trow = (c < 22) ? 6 : ((c < 43) ? hh : ww);
        const float cv = fcos[trow * 64 + c];
        const float sv = fsin[trow * 64 + c];
        const int base = head * HD + 2 * c;
        const float xr = row[base] * scale * g[base];
        const float xi = row[base + 1] * scale * g[base + 1];
        row[base]     = xr * cv - xi * sv;
        row[base + 1] = xr * sv + xi * cv;
    }
}

// ---------------------------------------------------------------------------
// tf32 tensor-core flash attention. Tile: 128 q x 64 k, HD=128.
// 256 threads = 8 warps (4x2):
//   score phase: warp = 32 q rows x 32 k cols
//   PV phase:    warp = 32 q rows x 64 hd cols
// ---------------------------------------------------------------------------
#define BQ 128
#define BK 64
#define KSTR 132
#define PSTR 68

struct AttnSmem {
    unsigned int Qs[BQ * KSTR];   // 128 x 132
    unsigned int KVs[BK * KSTR];  // 64 x 132 (K, then reused for V)
    float Ps[BQ * PSTR];          // 128 x 68 (fp32 scores -> tf32 bits)
    float row_m[BQ];
    float row_l[BQ];
    float row_a[BQ];
};
#define ATTN_SMEM ((int)sizeof(AttnSmem))

__global__ __launch_bounds__(256, 1)
void attn_tc_kernel(const float* __restrict__ q, const float* __restrict__ knew,
                    const float* __restrict__ vnew, const float* __restrict__ ck,
                    const float* __restrict__ cv, float* __restrict__ out) {
    extern __shared__ char smraw[];
    AttnSmem* sm = (AttnSmem*)smraw;

    const int head = blockIdx.y;
    const int q0 = blockIdx.x * BQ;
    const int tid = threadIdx.x;
    const int lane = tid & 31;
    const int w = tid >> 5;
    const int g = lane >> 2;
    const int tg = lane & 3;
    const int wy = w >> 1;      // 0..3 -> q-row group *32
    const int wx = w & 1;       // score: k-col *32 ; PV: hd-col *64

    // ---- load Q tile (tf32), zero-pad tail rows ----
    {
        const int r = tid >> 1;             // 0..127
        const int cbase = (tid & 1) * 64;
        const int srow = q0 + r;
        const bool valid = srow < S_TOK;
        const float* src = q + (size_t)srow * DIM + head * HD;
#pragma unroll
        for (int m2 = 0; m2 < 16; m2++) {
            int d = cbase + m2 * 4;
            float4 v = valid ? *(const float4*)(src + d) : make_float4(0.f, 0.f, 0.f, 0.f);
            *(uint4*)&sm->Qs[r * KSTR + d] =
                make_uint4(f2tf(v.x), f2tf(v.y), f2tf(v.z), f2tf(v.w));
        }
    }
    if (tid < BQ) { sm->row_m[tid] = -1e30f; sm->row_l[tid] = 0.f; }

    float acc[2][8][4];
#pragma unroll
    for (int mf = 0; mf < 2; mf++)
#pragma unroll
        for (int nf = 0; nf < 8; nf++)
#pragma unroll
            for (int j = 0; j < 4; j++) acc[mf][nf][j] = 0.f;

    __syncthreads();

    const int NT = (L_TOT + BK - 1) / BK;  // 171
    for (int t = 0; t < NT; t++) {
        const int kbase = t * BK;

        // ---- load K tile (tf32) ----
        {
            const int r = tid >> 2;
            const int cbase = (tid & 3) * 32;
            const int kidx = kbase + r;
            const bool valid = kidx < L_TOT;
            const float* src = (kidx < CUR)
                ? (ck + ((size_t)kidx * NH + head) * HD)
                : (knew + (size_t)(kidx - CUR) * DIM + head * HD);
#pragma unroll
            for (int m2 = 0; m2 < 8; m2++) {
                int d = cbase + m2 * 4;
                float4 v = valid ? *(const float4*)(src + d) : make_float4(0.f, 0.f, 0.f, 0.f);
                *(uint4*)&sm->KVs[r * KSTR + d] =
                    make_uint4(f2tf(v.x), f2tf(v.y), f2tf(v.z), f2tf(v.w));
            }
        }
        __syncthreads();

        // ---- scores: warp = 32q x 32k ----
        {
            float sc[2][4][4];
#pragma unroll
            for (int mf = 0; mf < 2; mf++)
#pragma unroll
                for (int nf = 0; nf < 4; nf++)
#pragma unroll
                    for (int j = 0; j < 4; j++) sc[mf][nf][j] = 0.f;

#pragma unroll 4
            for (int kf = 0; kf < 16; kf++) {
                const int kc = kf * 8;
                unsigned int a[2][4];
#pragma unroll
                for (int mf = 0; mf < 2; mf++) {
                    const int row = wy * 32 + mf * 16 + g;
                    a[mf][0] = sm->Qs[row * KSTR + kc + tg];
                    a[mf][1] = sm->Qs[(row + 8) * KSTR + kc + tg];
                    a[mf][2] = sm->Qs[row * KSTR + kc + tg + 4];
                    a[mf][3] = sm->Qs[(row + 8) * KSTR + kc + tg + 4];
                }
#pragma unroll
                for (int nf = 0; nf < 4; nf++) {
                    const int brow = wx * 32 + nf * 8 + g;
                    unsigned int b0 = sm->KVs[brow * KSTR + kc + tg];
                    unsigned int b1 = sm->KVs[brow * KSTR + kc + tg + 4];
                    mma_tf32(sc[0][nf], a[0][0], a[0][1], a[0][2], a[0][3], b0, b1);
                    mma_tf32(sc[1][nf], a[1][0], a[1][1], a[1][2], a[1][3], b0, b1);
                }
            }
            // write scores (scaled, masked) to Ps as fp32
#pragma unroll
            for (int mf = 0; mf < 2; mf++) {
                const int row = wy * 32 + mf * 16 + g;
#pragma unroll
                for (int nf = 0; nf < 4; nf++) {
                    const int col = wx * 32 + nf * 8 + 2 * tg;
                    const int kidx = kbase + col;
                    const bool v0 = kidx < L_TOT;
                    const bool v1 = kidx + 1 < L_TOT;
                    sm->Ps[row * PSTR + col]           = v0 ? sc[mf][nf][0] * SCALE : -1e30f;
                    sm->Ps[row * PSTR + col + 1]       = v1 ? sc[mf][nf][1] * SCALE : -1e30f;
                    sm->Ps[(row + 8) * PSTR + col]     = v0 ? sc[mf][nf][2] * SCALE : -1e30f;
                    sm->Ps[(row + 8) * PSTR + col + 1] = v1 ? sc[mf][nf][3] * SCALE : -1e30f;
                }
            }
        }
        __syncthreads();

        // ---- softmax update (2 threads/row), exp written back as tf32 bits ----
        {
            const int r = tid >> 1;         // 0..127
            const int part = tid & 1;
            float mx = -1e30f;
#pragma unroll
            for (int jj = 0; jj < 32; jj++)
                mx = fmaxf(mx, sm->Ps[r * PSTR + part * 32 + jj]);
            mx = fmaxf(mx, __shfl_xor_sync(0xffffffffu, mx, 1));
            const float m_old = sm->row_m[r];
            const float m_new = fmaxf(m_old, mx);
            float sum = 0.f;
            unsigned int* Pu = (unsigned int*)sm->Ps;
#pragma unroll
            for (int jj = 0; jj < 32; jj++) {
                float p = __expf(sm->Ps[r * PSTR + part * 32 + jj] - m_new);
                Pu[r * PSTR + part * 32 + jj] = f2tf(p);
                sum += p;
            }
            sum += __shfl_xor_sync(0xffffffffu, sum, 1);
            if (part == 0) {
                const float al = __expf(m_old - m_new);
                sm->row_a[r] = al;
                sm->row_l[r] = sm->row_l[r] * al + sum;
                sm->row_m[r] = m_new;
            }
        }
        // ---- load V tile into KVs ----
        {
            const int r = tid >> 2;
            const int cbase = (tid & 3) * 32;
            const int kidx = kbase + r;
            const bool valid = kidx < L_TOT;
            const float* src = (kidx < CUR)
                ? (cv + ((size_t)kidx * NH + head) * HD)
                : (vnew + (size_t)(kidx - CUR) * DIM + head * HD);
#pragma unroll
            for (int m2 = 0; m2 < 8; m2++) {
                int d = cbase + m2 * 4;
                float4 v = valid ? *(const float4*)(src + d) : make_float4(0.f, 0.f, 0.f, 0.f);
                *(uint4*)&sm->KVs[r * KSTR + d] =
                    make_uint4(f2tf(v.x), f2tf(v.y), f2tf(v.z), f2tf(v.w));
            }
        }
        __syncthreads();

        // ---- PV: warp = 32q x 64hd over 64 k ----
        {
#pragma unroll
            for (int mf = 0; mf < 2; mf++) {
                const int row = wy * 32 + mf * 16 + g;
                const float aA = sm->row_a[row];
                const float aB = sm->row_a[row + 8];
#pragma unroll
                for (int nf = 0; nf < 8; nf++) {
                    acc[mf][nf][0] *= aA; acc[mf][nf][1] *= aA;
                    acc[mf][nf][2] *= aB; acc[mf][nf][3] *= aB;
                }
            }
            const unsigned int* Pu = (const unsigned int*)sm->Ps;
#pragma unroll 4
            for (int kf = 0; kf < 8; kf++) {
                const int kc = kf * 8;
                unsigned int a[2][4];
#pragma unroll
                for (int mf = 0; mf < 2; mf++) {
                    const int row = wy * 32 + mf * 16 + g;
                    a[mf][0] = Pu[row * PSTR + kc + tg];
                    a[mf][1] = Pu[(row + 8) * PSTR + kc + tg];
                    a[mf][2] = Pu[row * PSTR + kc + tg + 4];
                    a[mf][3] = Pu[(row + 8) * PSTR + kc + tg + 4];
                }
#pragma unroll
                for (int nf = 0; nf < 8; nf++) {
                    unsigned int b0 = sm->KVs[(kc + tg) * KSTR + wx * 64 + nf * 8 + g];
                    unsigned int b1 = sm->KVs[(kc + tg + 4) * KSTR + wx * 64 + nf * 8 + g];
                    mma_tf32(acc[0][nf], a[0][0], a[0][1], a[0][2], a[0][3], b0, b1);
                    mma_tf32(acc[1][nf], a[1][0], a[1][1], a[1][2], a[1][3], b0, b1);
                }
            }
        }
        __syncthreads();
    }

    // ---- epilogue ----
#pragma unroll
    for (int mf = 0; mf < 2; mf++) {
        const int rbase = wy * 32 + mf * 16 + g;
        const float inv  = 1.0f / sm->row_l[rbase];
        const float inv8 = 1.0f / sm->row_l[rbase + 8];
        const int row  = q0 + rbase;
        const int row8 = row + 8;
#pragma unroll
        for (int nf = 0; nf < 8; nf++) {
            const int col = head * HD + wx * 64 + nf * 8 + 2 * tg;
            if (row < S_TOK)
                *(float2*)(out + (size_t)row * DIM + col) =
                    make_float2(acc[mf][nf][0] * inv, acc[mf][nf][1] * inv);
            if (row8 < S_TOK)
                *(float2*)(out + (size_t)row8 * DIM + col) =
                    make_float2(acc[mf][nf][2] * inv8, acc[mf][nf][3] * inv8);
        }
    }
}

// ---------------------------------------------------------------------------
extern "C" void kernel_launch(void* const* d_in, const int* in_sizes, int n_in,
                              void* d_out, int out_size) {
    (void)in_sizes; (void)n_in; (void)out_size;
    const float* x    = (const float*)d_in[0];
    const float* wq   = (const float*)d_in[1];
    const float* bq   = (const float*)d_in[2];
    const float* wk   = (const float*)d_in[3];
    const float* bk   = (const float*)d_in[4];
    const float* wv   = (const float*)d_in[5];
    const float* bv   = (const float*)d_in[6];
    const float* wo   = (const float*)d_in[7];
    const float* bo   = (const float*)d_in[8];
    const float* gq   = (const float*)d_in[9];
    const float* gk   = (const float*)d_in[10];
    const float* fcos = (const float*)d_in[11];
    const float* fsin = (const float*)d_in[12];
    const float* ck   = (const float*)d_in[13];
    const float* cvv  = (const float*)d_in[14];

    float *q, *k, *v, *o;
    cudaGetSymbolAddress((void**)&q, g_q);
    cudaGetSymbolAddress((void**)&k, g_k);
    cudaGetSymbolAddress((void**)&v, g_v);
    cudaGetSymbolAddress((void**)&o, g_o);

    cudaFuncSetAttribute(attn_tc_kernel, cudaFuncAttributeMaxDynamicSharedMemorySize,
                         ATTN_SMEM);

    dim3 ggrid(DIM / 128, (S_TOK + 127) / 128);  // (12, 13)
    gemm_tf32_kernel<<<ggrid, 256>>>(x, wq, bq, q, S_TOK);
    gemm_tf32_kernel<<<ggrid, 256>>>(x, wk, bk, k, S_TOK);
    gemm_tf32_kernel<<<ggrid, 256>>>(x, wv, bv, v, S_TOK);

    norm_rope_kernel<<<S_TOK, 256>>>(q, gq, fcos, fsin);
    norm_rope_kernel<<<S_TOK, 256>>>(k, gk, fcos, fsin);

    dim3 agrid((S_TOK + BQ - 1) / BQ, NH);  // (13, 12)
    attn_tc_kernel<<<agrid, 256, ATTN_SMEM>>>(q, k, v, ck, cvv, o);

    gemm_tf32_kernel<<<ggrid, 256>>>(o, wo, bo, (float*)d_out, S_TOK);
}

// round 4
// speedup vs baseline: 2.9062x; 1.7638x over previous
#include <cuda_runtime.h>
#include <math.h>

// Problem constants (fixed by setup_inputs)
#define DIM   1536
#define S_TOK 1560
#define NH    12
#define HD    128
#define CUR   9360          // current_start
#define L_TOT 10920         // KV window length (w0 = 0)
#define W_GRID 52
#define SCALE 0.08838834764831845f  // 1/sqrt(128)

// Scratch (allocation-free: __device__ globals)
__device__ float g_q[S_TOK * DIM];
__device__ float g_k[S_TOK * DIM];
__device__ float g_o[S_TOK * DIM];
// Unified tf32-rounded KV window, layout [token][head][hd] (stride DIM)
__device__ float g_ck[L_TOT * DIM];
__device__ float g_cv[L_TOT * DIM];

__device__ __forceinline__ unsigned int f2tf(float f) {
    unsigned int u;
    asm("cvt.rna.tf32.f32 %0, %1;" : "=r"(u) : "f"(f));
    return u;
}
__device__ __forceinline__ float f2tff(float f) { return __uint_as_float(f2tf(f)); }

__device__ __forceinline__ void mma_tf32(float c[4], unsigned int a0, unsigned int a1,
                                         unsigned int a2, unsigned int a3,
                                         unsigned int b0, unsigned int b1) {
    asm("mma.sync.aligned.m16n8k8.row.col.f32.tf32.tf32.f32 "
        "{%0,%1,%2,%3}, {%4,%5,%6,%7}, {%8,%9}, {%0,%1,%2,%3};"
        : "+f"(c[0]), "+f"(c[1]), "+f"(c[2]), "+f"(c[3])
        : "r"(a0), "r"(a1), "r"(a2), "r"(a3), "r"(b0), "r"(b1));
}

__device__ __forceinline__ void cp16(unsigned int s_addr, const void* gptr) {
    asm volatile("cp.async.ca.shared.global [%0], [%1], 16;\n"
                 :: "r"(s_addr), "l"(gptr));
}
__device__ __forceinline__ void cp_commit() {
    asm volatile("cp.async.commit_group;\n");
}
template <int N>
__device__ __forceinline__ void cp_wait() {
    asm volatile("cp.async.wait_group %0;\n" :: "n"(N));
}

// ---------------------------------------------------------------------------
// Preround: cache K/V -> tf32-rounded scratch (first CUR tokens)
// ---------------------------------------------------------------------------
__global__ __launch_bounds__(256)
void preround_kernel(const float* __restrict__ ck, const float* __restrict__ cv) {
    const size_t n = (size_t)CUR * DIM;
    size_t i = ((size_t)blockIdx.x * 256 + threadIdx.x) * 4;
    const size_t stride = (size_t)gridDim.x * 256 * 4;
    for (; i < n; i += stride) {
        float4 a = *(const float4*)(ck + i);
        float4 b = *(const float4*)(cv + i);
        *(float4*)(g_ck + i) = make_float4(f2tff(a.x), f2tff(a.y), f2tff(a.z), f2tff(a.w));
        *(float4*)(g_cv + i) = make_float4(f2tff(b.x), f2tff(b.y), f2tff(b.z), f2tff(b.w));
    }
}

// ---------------------------------------------------------------------------
// tf32 tensor-core GEMM: C = A @ B^T + bias. 128x128 tile, BK=32, 8 warps.
// Fused Q/K/V variant selects weights by blockIdx.z; V output tf32-rounded
// straight into the unified KV scratch.
// ---------------------------------------------------------------------------
#define GSTR 36

struct GemmOuts { const float *B, *bias; float* C; int rnd; };

__device__ __forceinline__ void gemm_body(const float* __restrict__ A,
                                          const float* __restrict__ B,
                                          const float* __restrict__ bias,
                                          float* __restrict__ C, int M, int rnd) {
    __shared__ unsigned int As[128 * GSTR];
    __shared__ unsigned int Bs[128 * GSTR];
    const int tid = threadIdx.x;
    const int m0 = blockIdx.y * 128;
    const int n0 = blockIdx.x * 128;
    const int lane = tid & 31;
    const int w = tid >> 5;
    const int g = lane >> 2;
    const int tg = lane & 3;
    const int wy = w >> 1;
    const int wx = w & 1;
    const int r = tid >> 1;
    const int cbase = (tid & 1) * 16;

    float acc[2][8][4];
#pragma unroll
    for (int mf = 0; mf < 2; mf++)
#pragma unroll
        for (int nf = 0; nf < 8; nf++)
#pragma unroll
            for (int j = 0; j < 4; j++) acc[mf][nf][j] = 0.f;

    const bool avalid = (m0 + r) < M;
    const float* pa = A + (size_t)(m0 + r) * DIM + cbase;
    const float* pb = B + (size_t)(n0 + r) * DIM + cbase;

    for (int k0 = 0; k0 < DIM; k0 += 32) {
#pragma unroll
        for (int i = 0; i < 4; i++) {
            float4 v = avalid ? *(const float4*)(pa + k0 + i * 4)
                              : make_float4(0.f, 0.f, 0.f, 0.f);
            *(uint4*)&As[r * GSTR + cbase + i * 4] =
                make_uint4(f2tf(v.x), f2tf(v.y), f2tf(v.z), f2tf(v.w));
        }
#pragma unroll
        for (int i = 0; i < 4; i++) {
            float4 v = *(const float4*)(pb + k0 + i * 4);
            *(uint4*)&Bs[r * GSTR + cbase + i * 4] =
                make_uint4(f2tf(v.x), f2tf(v.y), f2tf(v.z), f2tf(v.w));
        }
        __syncthreads();
#pragma unroll
        for (int kc = 0; kc < 32; kc += 8) {
            unsigned int a[2][4];
#pragma unroll
            for (int mf = 0; mf < 2; mf++) {
                const int row = wy * 32 + mf * 16 + g;
                a[mf][0] = As[row * GSTR + kc + tg];
                a[mf][1] = As[(row + 8) * GSTR + kc + tg];
                a[mf][2] = As[row * GSTR + kc + tg + 4];
                a[mf][3] = As[(row + 8) * GSTR + kc + tg + 4];
            }
#pragma unroll
            for (int nf = 0; nf < 8; nf++) {
                const int brow = wx * 64 + nf * 8 + g;
                unsigned int b0 = Bs[brow * GSTR + kc + tg];
                unsigned int b1 = Bs[brow * GSTR + kc + tg + 4];
                mma_tf32(acc[0][nf], a[0][0], a[0][1], a[0][2], a[0][3], b0, b1);
                mma_tf32(acc[1][nf], a[1][0], a[1][1], a[1][2], a[1][3], b0, b1);
            }
        }
        __syncthreads();
    }

#pragma unroll
    for (int mf = 0; mf < 2; mf++) {
        const int row = m0 + wy * 32 + mf * 16 + g;
#pragma unroll
        for (int nf = 0; nf < 8; nf++) {
            const int col = n0 + wx * 64 + nf * 8 + 2 * tg;
            const float b0 = bias[col], b1 = bias[col + 1];
            float v00 = acc[mf][nf][0] + b0, v01 = acc[mf][nf][1] + b1;
            float v10 = acc[mf][nf][2] + b0, v11 = acc[mf][nf][3] + b1;
            if (rnd) { v00 = f2tff(v00); v01 = f2tff(v01); v10 = f2tff(v10); v11 = f2tff(v11); }
            if (row < M)
                *(float2*)(C + (size_t)row * DIM + col) = make_float2(v00, v01);
            if (row + 8 < M)
                *(float2*)(C + (size_t)(row + 8) * DIM + col) = make_float2(v10, v11);
        }
    }
}

__global__ __launch_bounds__(256, 2)
void gemm_qkv_kernel(const float* __restrict__ A,
                     const float* __restrict__ wq, const float* __restrict__ bq,
                     const float* __restrict__ wk, const float* __restrict__ bk,
                     const float* __restrict__ wv, const float* __restrict__ bv,
                     int M) {
    const float *B, *bias; float* C; int rnd;
    if (blockIdx.z == 0)      { B = wq; bias = bq; C = g_q; rnd = 0; }
    else if (blockIdx.z == 1) { B = wk; bias = bk; C = g_k; rnd = 0; }
    else                      { B = wv; bias = bv; C = g_cv + (size_t)CUR * DIM; rnd = 1; }
    gemm_body(A, B, bias, C, M, rnd);
}

__global__ __launch_bounds__(256, 2)
void gemm_out_kernel(const float* __restrict__ A, const float* __restrict__ B,
                     const float* __restrict__ bias, float* __restrict__ C, int M) {
    gemm_body(A, B, bias, C, M, 0);
}

// ---------------------------------------------------------------------------
// rmsnorm + RoPE, tf32-rounded output to dst (may differ from src)
// ---------------------------------------------------------------------------
__global__ __launch_bounds__(256)
void norm_rope_kernel(const float* __restrict__ src, float* __restrict__ dst,
                      const float* __restrict__ g,
                      const float* __restrict__ fcos, const float* __restrict__ fsin) {
    const int s = blockIdx.x;
    const float* row = src + (size_t)s * DIM;
    float* orow = dst + (size_t)s * DIM;
    __shared__ float red[256];

    float ss = 0.f;
    for (int i = threadIdx.x; i < DIM; i += 256) {
        float v = row[i];
        ss += v * v;
    }
    red[threadIdx.x] = ss;
    __syncthreads();
    for (int off = 128; off > 0; off >>= 1) {
        if (threadIdx.x < off) red[threadIdx.x] += red[threadIdx.x + off];
        __syncthreads();
    }
    const float scale = rsqrtf(red[0] * (1.0f / DIM) + 1e-6f);

    const int hh = s / W_GRID;
    const int ww = s % W_GRID;
    for (int p = threadIdx.x; p < NH * 64; p += 256) {
        const int head = p >> 6;
        const int c = p & 63;
        const int trow = (c < 22) ? 6 : ((c < 43) ? hh : ww);
        const float cv = fcos[trow * 64 + c];
        const float sv = fsin[trow * 64 + c];
        const int base = head * HD + 2 * c;
        const float xr = row[base] * scale * g[base];
        const float xi = row[base + 1] * scale * g[base + 1];
        orow[base]     = f2tff(xr * cv - xi * sv);
        orow[base + 1] = f2tff(xr * sv + xi * cv);
    }
}

// ---------------------------------------------------------------------------
// tf32 flash attention. BQ=144 q x BK=64 k tiles, 9 warps (288 threads).
// Grid = 11 x 12 = 132 blocks -> single wave on 148 SMs.
// cp.async double-buffer: V(t) prefetched during score, K(t+1) during PV.
// Score: warp = 16q x 64k.  PV: warp = 16q x 128hd.
// ---------------------------------------------------------------------------
#define BQ 144
#define BK 64
#define QSTR 132
#define KSTR 132
#define VSTR 136
#define PSTR 68
#define NTHR 288

struct AttnSmem {
    unsigned int Qs[BQ * QSTR];
    unsigned int Ks[BK * KSTR];
    unsigned int Vs[BK * VSTR];
    float Ps[BQ * PSTR];
    float row_m[BQ];
    float row_l[BQ];
    float row_a[BQ];
};
#define ATTN_SMEM ((int)sizeof(AttnSmem))

__global__ __launch_bounds__(NTHR, 1)
void attn_tc_kernel(const float* __restrict__ q, float* __restrict__ out) {
    extern __shared__ char smraw[];
    AttnSmem* sm = (AttnSmem*)smraw;

    const int head = blockIdx.y;
    const int q0 = blockIdx.x * BQ;
    const int tid = threadIdx.x;
    const int lane = tid & 31;
    const int w = tid >> 5;          // 0..8
    const int g = lane >> 2;
    const int tg = lane & 3;
    const int wq = w * 16;           // q-row base for this warp

    const unsigned int smem_base = (unsigned int)__cvta_generic_to_shared(sm);
    const unsigned int ks_base = smem_base + (unsigned int)((char*)sm->Ks - (char*)sm);
    const unsigned int vs_base = smem_base + (unsigned int)((char*)sm->Vs - (char*)sm);

    // K/V loader role: threads 0..255, 8x16B cp.async each
    const int lr = tid >> 2;            // 0..63 (if tid<256)
    const int lc = (tid & 3) * 32;      // float col base
    const bool loader = tid < 256;

    // ---- load Q tile (pre-rounded tf32 bits), zero-pad tail rows ----
    {
        const int r = tid >> 1;          // 0..143
        const int cbase = (tid & 1) * 64;
        const int srow = q0 + r;
        const bool valid = srow < S_TOK;
        const float* src = q + (size_t)srow * DIM + head * HD;
#pragma unroll
        for (int m2 = 0; m2 < 16; m2++) {
            int d = cbase + m2 * 4;
            float4 v = valid ? *(const float4*)(src + d) : make_float4(0.f, 0.f, 0.f, 0.f);
            *(float4*)&sm->Qs[r * QSTR + d] = v;
        }
    }
    if (tid < BQ) { sm->row_m[tid] = -1e30f; sm->row_l[tid] = 0.f; }

    float acc[16][4];
#pragma unroll
    for (int nf = 0; nf < 16; nf++)
#pragma unroll
        for (int j = 0; j < 4; j++) acc[nf][j] = 0.f;

    const int NT = (L_TOT + BK - 1) / BK;  // 171

    // prologue: issue K(0)
    if (loader) {
        const int kidx = min(0 * BK + lr, L_TOT - 1);
        const float* src = g_ck + (size_t)kidx * DIM + head * HD + lc;
#pragma unroll
        for (int i = 0; i < 8; i++)
            cp16(ks_base + (lr * KSTR + lc + i * 4) * 4, src + i * 4);
    }
    cp_commit();
    __syncthreads();   // Q visible

    for (int t = 0; t < NT; t++) {
        const int kbase = t * BK;

        // issue V(t)
        if (loader) {
            const int kidx = min(kbase + lr, L_TOT - 1);
            const float* src = g_cv + (size_t)kidx * DIM + head * HD + lc;
#pragma unroll
            for (int i = 0; i < 8; i++)
                cp16(vs_base + (lr * VSTR + lc + i * 4) * 4, src + i * 4);
        }
        cp_commit();

        cp_wait<1>();      // K(t) complete (V(t) may be in flight)
        __syncthreads();

        // ---- scores: warp = 16q x 64k ----
        {
            float sc[8][4];
#pragma unroll
            for (int nf = 0; nf < 8; nf++)
#pragma unroll
                for (int j = 0; j < 4; j++) sc[nf][j] = 0.f;

#pragma unroll 4
            for (int kf = 0; kf < 16; kf++) {
                const int kc = kf * 8;
                unsigned int a0 = sm->Qs[(wq + g) * QSTR + kc + tg];
                unsigned int a1 = sm->Qs[(wq + g + 8) * QSTR + kc + tg];
                unsigned int a2 = sm->Qs[(wq + g) * QSTR + kc + tg + 4];
                unsigned int a3 = sm->Qs[(wq + g + 8) * QSTR + kc + tg + 4];
#pragma unroll
                for (int nf = 0; nf < 8; nf++) {
                    unsigned int b0 = sm->Ks[(nf * 8 + g) * KSTR + kc + tg];
                    unsigned int b1 = sm->Ks[(nf * 8 + g) * KSTR + kc + tg + 4];
                    mma_tf32(sc[nf], a0, a1, a2, a3, b0, b1);
                }
            }
#pragma unroll
            for (int nf = 0; nf < 8; nf++) {
                const int col = nf * 8 + 2 * tg;
                const int kidx = kbase + col;
                const bool v0 = kidx < L_TOT;
                const bool v1 = kidx + 1 < L_TOT;
                sm->Ps[(wq + g) * PSTR + col]           = v0 ? sc[nf][0] * SCALE : -1e30f;
                sm->Ps[(wq + g) * PSTR + col + 1]       = v1 ? sc[nf][1] * SCALE : -1e30f;
                sm->Ps[(wq + g + 8) * PSTR + col]       = v0 ? sc[nf][2] * SCALE : -1e30f;
                sm->Ps[(wq + g + 8) * PSTR + col + 1]   = v1 ? sc[nf][3] * SCALE : -1e30f;
            }
        }
        __syncthreads();   // Ps visible; Ks free

        // issue K(t+1) (clamped re-issue on last iter keeps wait counts uniform)
        if (loader) {
            const int kidx = min(min(t + 1, NT - 1) * BK + lr, L_TOT - 1);
            const float* src = g_ck + (size_t)kidx * DIM + head * HD + lc;
#pragma unroll
            for (int i = 0; i < 8; i++)
                cp16(ks_base + (lr * KSTR + lc + i * 4) * 4, src + i * 4);
        }
        cp_commit();

        // ---- softmax (2 threads per row) ----
        {
            const int r = tid >> 1;        // 0..143
            const int part = tid & 1;
            float mx = -1e30f;
#pragma unroll
            for (int jj = 0; jj < 32; jj++)
                mx = fmaxf(mx, sm->Ps[r * PSTR + part * 32 + jj]);
            mx = fmaxf(mx, __shfl_xor_sync(0xffffffffu, mx, 1));
            const float m_old = sm->row_m[r];
            const float m_new = fmaxf(m_old, mx);
            float sum = 0.f;
            unsigned int* Pu = (unsigned int*)sm->Ps;
#pragma unroll
            for (int jj = 0; jj < 32; jj++) {
                float p = __expf(sm->Ps[r * PSTR + part * 32 + jj] - m_new);
                Pu[r * PSTR + part * 32 + jj] = f2tf(p);
                sum += p;
            }
            sum += __shfl_xor_sync(0xffffffffu, sum, 1);
            if (part == 0) {
                const float al = __expf(m_old - m_new);
                sm->row_a[r] = al;
                sm->row_l[r] = sm->row_l[r] * al + sum;
                sm->row_m[r] = m_new;
            }
        }

        cp_wait<1>();      // V(t) complete (K(t+1) may be in flight)
        __syncthreads();   // Vs + softmax results visible

        // ---- PV: warp = 16q x 128hd over 64 k ----
        {
            const float aA = sm->row_a[wq + g];
            const float aB = sm->row_a[wq + g + 8];
#pragma unroll
            for (int nf = 0; nf < 16; nf++) {
                acc[nf][0] *= aA; acc[nf][1] *= aA;
                acc[nf][2] *= aB; acc[nf][3] *= aB;
            }
            const unsigned int* Pu = (const unsigned int*)sm->Ps;
#pragma unroll 2
            for (int kf = 0; kf < 8; kf++) {
                const int kc = kf * 8;
                unsigned int a0 = Pu[(wq + g) * PSTR + kc + tg];
                unsigned int a1 = Pu[(wq + g + 8) * PSTR + kc + tg];
                unsigned int a2 = Pu[(wq + g) * PSTR + kc + tg + 4];
                unsigned int a3 = Pu[(wq + g + 8) * PSTR + kc + tg + 4];
#pragma unroll
                for (int nf = 0; nf < 16; nf++) {
                    unsigned int b0 = sm->Vs[(kc + tg) * VSTR + nf * 8 + g];
                    unsigned int b1 = sm->Vs[(kc + tg + 4) * VSTR + nf * 8 + g];
                    mma_tf32(acc[nf], a0, a1, a2, a3, b0, b1);
                }
            }
        }
        __syncthreads();   // Vs/Ps free for next iteration
    }

    // ---- epilogue ----
    {
        const float inv  = 1.0f / sm->row_l[wq + g];
        const float inv8 = 1.0f / sm->row_l[wq + g + 8];
        const int row  = q0 + wq + g;
        const int row8 = row + 8;
#pragma unroll
        for (int nf = 0; nf < 16; nf++) {
            const int col = head * HD + nf * 8 + 2 * tg;
            if (row < S_TOK)
                *(float2*)(out + (size_t)row * DIM + col) =
                    make_float2(acc[nf][0] * inv, acc[nf][1] * inv);
            if (row8 < S_TOK)
                *(float2*)(out + (size_t)row8 * DIM + col) =
                    make_float2(acc[nf][2] * inv8, acc[nf][3] * inv8);
        }
    }
}

// ---------------------------------------------------------------------------
extern "C" void kernel_launch(void* const* d_in, const int* in_sizes, int n_in,
                              void* d_out, int out_size) {
    (void)in_sizes; (void)n_in; (void)out_size;
    const float* x    = (const float*)d_in[0];
    const float* wq   = (const float*)d_in[1];
    const float* bq   = (const float*)d_in[2];
    const float* wk   = (const float*)d_in[3];
    const float* bk   = (const float*)d_in[4];
    const float* wv   = (const float*)d_in[5];
    const float* bv   = (const float*)d_in[6];
    const float* wo   = (const float*)d_in[7];
    const float* bo   = (const float*)d_in[8];
    const float* gq   = (const float*)d_in[9];
    const float* gk   = (const float*)d_in[10];
    const float* fcos = (const float*)d_in[11];
    const float* fsin = (const float*)d_in[12];
    const float* ck   = (const float*)d_in[13];
    const float* cvv  = (const float*)d_in[14];

    float *q, *k, *o, *gck;
    cudaGetSymbolAddress((void**)&q, g_q);
    cudaGetSymbolAddress((void**)&k, g_k);
    cudaGetSymbolAddress((void**)&o, g_o);
    cudaGetSymbolAddress((void**)&gck, g_ck);

    cudaFuncSetAttribute(attn_tc_kernel, cudaFuncAttributeMaxDynamicSharedMemorySize,
                         ATTN_SMEM);

    // 1. preround cache K/V into unified tf32 scratch
    preround_kernel<<<1024, 256>>>(ck, cvv);

    // 2. fused Q/K/V projections (V rounds straight into g_cv tail)
    dim3 qkvgrid(DIM / 128, (S_TOK + 127) / 128, 3);  // (12, 13, 3)
    gemm_qkv_kernel<<<qkvgrid, 256>>>(x, wq, bq, wk, bk, wv, bv, S_TOK);

    // 3. norm + rope: q in place; k appended (rounded) to g_ck tail
    norm_rope_kernel<<<S_TOK, 256>>>(q, q, gq, fcos, fsin);
    norm_rope_kernel<<<S_TOK, 256>>>(k, gck + (size_t)CUR * DIM, gk, fcos, fsin);

    // 4. attention (single wave: 132 blocks)
    dim3 agrid((S_TOK + BQ - 1) / BQ, NH);  // (11, 12)
    attn_tc_kernel<<<agrid, NTHR, ATTN_SMEM>>>(q, o);

    // 5. output projection
    dim3 ogrid(DIM / 128, (S_TOK + 127) / 128);  // (12, 13)
    gemm_out_kernel<<<ogrid, 256>>>(o, wo, bo, (float*)d_out, S_TOK);
}